// round 10
// baseline (speedup 1.0000x reference)
#include <cuda_runtime.h>
#include <cuda_bf16.h>
#include <cuda_fp8.h>
#include <cstdint>

// ============================================================================
// y[M,N] = fq(x*sx)[M,K] @ fq(w*sw)[N,K]^T / (sx*sw) + bias, bf16-rounded,
// stored as f32. fp8 mma.sync.m16n8k32 GEMM (bit-exact validated, R9).
// R10: 16 warps (4/SMSP) for latency hiding, warp tile 32x64, 1 barrier/chunk.
// ============================================================================
#define GM 8192
#define GN 4096
#define GK 4096

#define BM 128
#define BN 256
#define BK 128                     // fp8 bytes (= elems) per K chunk
#define K_CHUNKS (GK / BK)         // 32
#define STAGES 4
#define THREADS 512

#define A_BYTES (BM * BK)          // 16384
#define B_BYTES (BN * BK)          // 32768
#define STAGE_BYTES (A_BYTES + B_BYTES)      // 49152
#define SMEM_TOTAL (STAGES * STAGE_BYTES)    // 196608

// fp8 scratch, plain row-major [M][K] / [N][K]
__device__ __align__(128) unsigned char g_Aq[(size_t)GM * GK];
__device__ __align__(128) unsigned char g_Bq[(size_t)GN * GK];

// ============================================================================
// helpers
// ============================================================================
__device__ __forceinline__ uint32_t smem_to_u32(const void* p) {
    uint32_t a;
    asm("{ .reg .u64 t; cvta.to.shared.u64 t, %1; cvt.u32.u64 %0, t; }" : "=r"(a) : "l"(p));
    return a;
}
__device__ __forceinline__ void cp_async16(uint32_t dst_smem, const void* src) {
    asm volatile("cp.async.cg.shared.global [%0], [%1], 16;"
                 :: "r"(dst_smem), "l"(src) : "memory");
}
#define CP_COMMIT() asm volatile("cp.async.commit_group;" ::: "memory")
#define CP_WAIT2()  asm volatile("cp.async.wait_group 2;" ::: "memory")
#define CP_WAIT0()  asm volatile("cp.async.wait_group 0;" ::: "memory")

__device__ __forceinline__ void ldmatrix_x4(uint32_t& r0, uint32_t& r1,
                                            uint32_t& r2, uint32_t& r3, uint32_t addr) {
    asm volatile("ldmatrix.sync.aligned.m8n8.x4.shared.b16 {%0,%1,%2,%3}, [%4];"
                 : "=r"(r0), "=r"(r1), "=r"(r2), "=r"(r3) : "r"(addr));
}

__device__ __forceinline__ void mma_e4m3(float* d, const uint32_t* a,
                                         uint32_t b0, uint32_t b1) {
    asm volatile(
        "mma.sync.aligned.m16n8k32.row.col.f32.e4m3.e4m3.f32 "
        "{%0,%1,%2,%3}, {%4,%5,%6,%7}, {%8,%9}, {%0,%1,%2,%3};"
        : "+f"(d[0]), "+f"(d[1]), "+f"(d[2]), "+f"(d[3])
        : "r"(a[0]), "r"(a[1]), "r"(a[2]), "r"(a[3]), "r"(b0), "r"(b1));
}

// ----------------------------------------------------------------------------
// Exact reference fake-quant (E4M3). Bit-exact vs reference (R8/R9: rel_err=0).
// ----------------------------------------------------------------------------
__device__ __forceinline__ float fake_quant_e4m3(float y) {
    float yc = fminf(fmaxf(y, -448.0f), 448.0f);
    float mag = fabsf(yc);
    if (mag == 0.0f) return 0.0f;
    int e = (int)((__float_as_uint(mag) >> 23) & 0xFF) - 127;
    if (e < -6) e = -6;
    float stepinv = __int_as_float((uint32_t)(127 + 3 - e) << 23);  // 2^(3-e)
    float step    = __int_as_float((uint32_t)(127 - 3 + e) << 23);  // 2^(e-3)
    return rintf(yc * stepinv) * step;
}

// ============================================================================
// Quantization: f32 -> exact fake-quant -> e4m3 byte, row-major fp8 scratch.
// ============================================================================
__global__ void quant_kernel(const float* __restrict__ src,
                             const float* __restrict__ scale_p,
                             unsigned char* __restrict__ dst, int total8) {
    int idx = blockIdx.x * blockDim.x + threadIdx.x;
    if (idx >= total8) return;
    const float s = scale_p[0];
    size_t e0 = (size_t)idx * 8;
    float4 v0 = *reinterpret_cast<const float4*>(src + e0);
    float4 v1 = *reinterpret_cast<const float4*>(src + e0 + 4);
    float f[8] = {v0.x, v0.y, v0.z, v0.w, v1.x, v1.y, v1.z, v1.w};
    uint64_t out8 = 0;
#pragma unroll
    for (int i = 0; i < 8; i++) {
        float q = fake_quant_e4m3(f[i] * s);
        uint8_t b = __nv_cvt_float_to_fp8(q, __NV_SATFINITE, __NV_E4M3);
        out8 |= (uint64_t)b << (8 * i);
    }
    *reinterpret_cast<uint64_t*>(dst + e0) = out8;
}

// ============================================================================
// FP8 GEMM: 128x256 CTA tile, 16 warps (32x64 each, 4/SMSP), 4-stage pipeline.
// ============================================================================
__global__ void __launch_bounds__(THREADS, 1) gemm_kernel(
    const float* __restrict__ bias,
    const float* __restrict__ xs, const float* __restrict__ ws,
    float* __restrict__ out) {
    extern __shared__ __align__(128) char smem[];
    const uint32_t smem_base = smem_to_u32(smem);
    const int tid = threadIdx.x;
    const int w = tid >> 5, l = tid & 31;
    const int warp_m = (w >> 2) * 32;     // 0,32,64,96
    const int warp_n = (w & 3) * 64;      // 0,64,128,192
    const int nt = blockIdx.x, mt = blockIdx.y;

    const unsigned char* Ag = g_Aq + (size_t)(mt * BM) * GK;
    const unsigned char* Bg = g_Bq + (size_t)(nt * BN) * GK;

    auto load_stage = [&](int s, int kc) {
        const uint32_t sa = smem_base + s * STAGE_BYTES;
        const uint32_t sb = sa + A_BYTES;
        // A: 1024 16B chunks (128 rows x 8), 512 threads -> 2 iters
#pragma unroll
        for (int i = 0; i < 2; i++) {
            int c = tid + i * THREADS;
            int row = c >> 3, cb = c & 7;
            cp_async16(sa + row * 128 + ((cb ^ (row & 7)) << 4),
                       Ag + (size_t)row * GK + kc * BK + cb * 16);
        }
        // B: 2048 16B chunks (256 rows x 8) -> 4 iters
#pragma unroll
        for (int i = 0; i < 4; i++) {
            int c = tid + i * THREADS;
            int row = c >> 3, cb = c & 7;
            cp_async16(sb + row * 128 + ((cb ^ (row & 7)) << 4),
                       Bg + (size_t)row * GK + kc * BK + cb * 16);
        }
        CP_COMMIT();
    };

    // accumulators: [mi 0..1][n8-tile 0..7][4]
    float d[2][8][4];
#pragma unroll
    for (int i = 0; i < 2; i++)
#pragma unroll
        for (int j = 0; j < 8; j++)
#pragma unroll
            for (int q = 0; q < 4; q++) d[i][j][q] = 0.0f;

    load_stage(0, 0);
    load_stage(1, 1);
    load_stage(2, 2);

    const int lr = l & 15;        // ldmatrix row-within-16
    const int lk = l >> 4;        // ldmatrix k-half (16B group select)

#pragma unroll 1
    for (int kc = 0; kc < K_CHUNKS; ++kc) {
        CP_WAIT2();
        __syncthreads();          // all warps done reading stage (kc-1)%4
        if (kc + 3 < K_CHUNKS) load_stage((kc + 3) & (STAGES - 1), kc + 3);

        const int s = kc & (STAGES - 1);
        const uint32_t sa = smem_base + s * STAGE_BYTES;
        const uint32_t sb = sa + A_BYTES;

#pragma unroll
        for (int ks = 0; ks < 4; ++ks) {    // 4 x (k=32 fp8) per 128B chunk
            uint32_t a[2][4], bf[4][4];
            const int kg = ks * 2 + lk;     // 16B group index (0..7)
#pragma unroll
            for (int mi = 0; mi < 2; mi++) {
                const int r = warp_m + mi * 16 + lr;
                ldmatrix_x4(a[mi][0], a[mi][1], a[mi][2], a[mi][3],
                            sa + r * 128 + (((kg ^ (r & 7)) & 7) << 4));
            }
#pragma unroll
            for (int j = 0; j < 4; j++) {
                const int r = warp_n + j * 16 + lr;
                ldmatrix_x4(bf[j][0], bf[j][1], bf[j][2], bf[j][3],
                            sb + r * 128 + (((kg ^ (r & 7)) & 7) << 4));
            }
#pragma unroll
            for (int mi = 0; mi < 2; mi++)
#pragma unroll
                for (int nj = 0; nj < 8; nj++) {
                    const int j = nj >> 1, h = nj & 1;
                    mma_e4m3(d[mi][nj], a[mi], bf[j][h], bf[j][2 + h]);
                }
        }
        // no bottom barrier: stage (kc+3)%4 written next iter was last read in
        // iter kc-1, which completed before next iter's top __syncthreads.
    }
    CP_WAIT0();

    // ---- epilogue: dequant + bias, bf16-round, f32 stores ----
    const float inv = 1.0f / (xs[0] * ws[0]);
    const int mrow = mt * BM + warp_m + (l >> 2);
    const int ncol0 = nt * BN + warp_n + 2 * (l & 3);

#pragma unroll
    for (int nj = 0; nj < 8; nj++) {
        const int n = ncol0 + nj * 8;
        const float b0 = bias[n];
        const float b1 = bias[n + 1];
#pragma unroll
        for (int mi = 0; mi < 2; mi++) {
            const int m0 = mrow + mi * 16;
            float f0 = __bfloat162float(__float2bfloat16_rn(d[mi][nj][0] * inv + b0));
            float f1 = __bfloat162float(__float2bfloat16_rn(d[mi][nj][1] * inv + b1));
            float f2 = __bfloat162float(__float2bfloat16_rn(d[mi][nj][2] * inv + b0));
            float f3 = __bfloat162float(__float2bfloat16_rn(d[mi][nj][3] * inv + b1));
            *reinterpret_cast<float2*>(out + (size_t)m0 * GN + n) = make_float2(f0, f1);
            *reinterpret_cast<float2*>(out + (size_t)(m0 + 8) * GN + n) = make_float2(f2, f3);
        }
    }
}

// ============================================================================
// kernel_launch — inputs identified by element count
// ============================================================================
extern "C" void kernel_launch(void* const* d_in, const int* in_sizes, int n_in,
                              void* d_out, int out_size) {
    const float* x = nullptr;
    const float* wgt = nullptr;
    const float* bias = nullptr;
    const float* scales[3] = {nullptr, nullptr, nullptr};
    int ns = 0;
    for (int i = 0; i < n_in; i++) {
        const int sz = in_sizes[i];
        if (sz == GM * GK)      x    = (const float*)d_in[i];
        else if (sz == GN * GK) wgt  = (const float*)d_in[i];
        else if (sz == GN)      bias = (const float*)d_in[i];
        else if (sz == 1 && ns < 3) scales[ns++] = (const float*)d_in[i];
    }
    const float* xs = scales[0];   // x_scale (first size-1 input)
    const float* ws = scales[1];   // w_scale (second size-1 input)
    float* out = (float*)d_out;

    unsigned char* aq; cudaGetSymbolAddress((void**)&aq, g_Aq);
    unsigned char* bq; cudaGetSymbolAddress((void**)&bq, g_Bq);

    {
        const int total8 = GM * GK / 8;
        quant_kernel<<<total8 / 256, 256>>>(x, xs, aq, total8);
    }
    {
        const int total8 = GN * GK / 8;
        quant_kernel<<<total8 / 256, 256>>>(wgt, ws, bq, total8);
    }

    cudaFuncSetAttribute(gemm_kernel, cudaFuncAttributeMaxDynamicSharedMemorySize, SMEM_TOTAL);
    dim3 grid(GN / BN, GM / BM);   // (16, 64) = 1024 CTAs
    gemm_kernel<<<grid, THREADS, SMEM_TOTAL>>>(bias, xs, ws, out);
}

// round 11
// speedup vs baseline: 1.0459x; 1.0459x over previous
#include <cuda_runtime.h>
#include <cuda_bf16.h>
#include <cuda_fp8.h>
#include <cstdint>

// ============================================================================
// y[M,N] = fq(x*sx)[M,K] @ fq(w*sw)[N,K]^T / (sx*sw) + bias, bf16-rounded,
// stored as f32. fp8 mma.sync.m16n8k32 GEMM (bit-exact, R9).
// R11: 128x128 tile, 96KB smem, 2 CTAs/SM — cross-CTA bubble filling.
// ============================================================================
#define GM 8192
#define GN 4096
#define GK 4096

#define BM 128
#define BN 128
#define BK 128                     // fp8 bytes (= elems) per K chunk
#define K_CHUNKS (GK / BK)         // 32
#define STAGES 3
#define THREADS 256

#define A_BYTES (BM * BK)          // 16384
#define B_BYTES (BN * BK)          // 16384
#define STAGE_BYTES (A_BYTES + B_BYTES)      // 32768
#define SMEM_TOTAL (STAGES * STAGE_BYTES)    // 98304 -> 2 CTAs/SM

// fp8 scratch, plain row-major [M][K] / [N][K]
__device__ __align__(128) unsigned char g_Aq[(size_t)GM * GK];
__device__ __align__(128) unsigned char g_Bq[(size_t)GN * GK];

// ============================================================================
// helpers
// ============================================================================
__device__ __forceinline__ uint32_t smem_to_u32(const void* p) {
    uint32_t a;
    asm("{ .reg .u64 t; cvta.to.shared.u64 t, %1; cvt.u32.u64 %0, t; }" : "=r"(a) : "l"(p));
    return a;
}
__device__ __forceinline__ void cp_async16(uint32_t dst_smem, const void* src) {
    asm volatile("cp.async.cg.shared.global [%0], [%1], 16;"
                 :: "r"(dst_smem), "l"(src) : "memory");
}
#define CP_COMMIT() asm volatile("cp.async.commit_group;" ::: "memory")
#define CP_WAIT1()  asm volatile("cp.async.wait_group 1;" ::: "memory")
#define CP_WAIT0()  asm volatile("cp.async.wait_group 0;" ::: "memory")

__device__ __forceinline__ void ldmatrix_x4(uint32_t& r0, uint32_t& r1,
                                            uint32_t& r2, uint32_t& r3, uint32_t addr) {
    asm volatile("ldmatrix.sync.aligned.m8n8.x4.shared.b16 {%0,%1,%2,%3}, [%4];"
                 : "=r"(r0), "=r"(r1), "=r"(r2), "=r"(r3) : "r"(addr));
}

__device__ __forceinline__ void mma_e4m3(float* d, const uint32_t* a,
                                         uint32_t b0, uint32_t b1) {
    asm volatile(
        "mma.sync.aligned.m16n8k32.row.col.f32.e4m3.e4m3.f32 "
        "{%0,%1,%2,%3}, {%4,%5,%6,%7}, {%8,%9}, {%0,%1,%2,%3};"
        : "+f"(d[0]), "+f"(d[1]), "+f"(d[2]), "+f"(d[3])
        : "r"(a[0]), "r"(a[1]), "r"(a[2]), "r"(a[3]), "r"(b0), "r"(b1));
}

// ----------------------------------------------------------------------------
// Exact reference fake-quant (E4M3). Bit-exact vs reference (R8-R10: rel=0).
// ----------------------------------------------------------------------------
__device__ __forceinline__ float fake_quant_e4m3(float y) {
    float yc = fminf(fmaxf(y, -448.0f), 448.0f);
    float mag = fabsf(yc);
    if (mag == 0.0f) return 0.0f;
    int e = (int)((__float_as_uint(mag) >> 23) & 0xFF) - 127;
    if (e < -6) e = -6;
    float stepinv = __int_as_float((uint32_t)(127 + 3 - e) << 23);  // 2^(3-e)
    float step    = __int_as_float((uint32_t)(127 - 3 + e) << 23);  // 2^(e-3)
    return rintf(yc * stepinv) * step;
}

// ============================================================================
// Merged quantization: one launch covers both x (-> g_Aq) and w (-> g_Bq).
// ============================================================================
#define X_TOTAL8 (GM * GK / 8)     // 4,194,304
#define W_TOTAL8 (GN * GK / 8)     // 2,097,152

__global__ void quant_both_kernel(const float* __restrict__ x,
                                  const float* __restrict__ wgt,
                                  const float* __restrict__ xs,
                                  const float* __restrict__ ws) {
    int idx = blockIdx.x * blockDim.x + threadIdx.x;
    const float* src;
    unsigned char* dst;
    float s;
    size_t e0;
    if (idx < X_TOTAL8) {
        src = x; dst = g_Aq; s = xs[0];
        e0 = (size_t)idx * 8;
    } else {
        idx -= X_TOTAL8;
        if (idx >= W_TOTAL8) return;
        src = wgt; dst = g_Bq; s = ws[0];
        e0 = (size_t)idx * 8;
    }
    float4 v0 = *reinterpret_cast<const float4*>(src + e0);
    float4 v1 = *reinterpret_cast<const float4*>(src + e0 + 4);
    float f[8] = {v0.x, v0.y, v0.z, v0.w, v1.x, v1.y, v1.z, v1.w};
    uint64_t out8 = 0;
#pragma unroll
    for (int i = 0; i < 8; i++) {
        float q = fake_quant_e4m3(f[i] * s);
        uint8_t b = __nv_cvt_float_to_fp8(q, __NV_SATFINITE, __NV_E4M3);
        out8 |= (uint64_t)b << (8 * i);
    }
    *reinterpret_cast<uint64_t*>(dst + e0) = out8;
}

// ============================================================================
// FP8 GEMM: 128x128 CTA tile, 8 warps (32x64 each), 3-stage pipeline,
// 2 CTAs/SM for cross-CTA bubble filling.
// ============================================================================
__global__ void __launch_bounds__(THREADS, 2) gemm_kernel(
    const float* __restrict__ bias,
    const float* __restrict__ xs, const float* __restrict__ ws,
    float* __restrict__ out) {
    extern __shared__ __align__(128) char smem[];
    const uint32_t smem_base = smem_to_u32(smem);
    const int tid = threadIdx.x;
    const int w = tid >> 5, l = tid & 31;
    const int warp_m = (w >> 1) * 32;     // 0,32,64,96
    const int warp_n = (w & 1) * 64;      // 0,64
    const int nt = blockIdx.x, mt = blockIdx.y;

    const unsigned char* Ag = g_Aq + (size_t)(mt * BM) * GK;
    const unsigned char* Bg = g_Bq + (size_t)(nt * BN) * GK;

    auto load_stage = [&](int s, int kc) {
        const uint32_t sa = smem_base + s * STAGE_BYTES;
        const uint32_t sb = sa + A_BYTES;
        // A: 1024 16B chunks (128 rows x 8), 256 threads -> 4 iters
#pragma unroll
        for (int i = 0; i < 4; i++) {
            int c = tid + i * THREADS;
            int row = c >> 3, cb = c & 7;
            cp_async16(sa + row * 128 + ((cb ^ (row & 7)) << 4),
                       Ag + (size_t)row * GK + kc * BK + cb * 16);
        }
        // B: 1024 16B chunks
#pragma unroll
        for (int i = 0; i < 4; i++) {
            int c = tid + i * THREADS;
            int row = c >> 3, cb = c & 7;
            cp_async16(sb + row * 128 + ((cb ^ (row & 7)) << 4),
                       Bg + (size_t)row * GK + kc * BK + cb * 16);
        }
        CP_COMMIT();
    };

    // accumulators: [mi 0..1][n8-tile 0..7][4]
    float d[2][8][4];
#pragma unroll
    for (int i = 0; i < 2; i++)
#pragma unroll
        for (int j = 0; j < 8; j++)
#pragma unroll
            for (int q = 0; q < 4; q++) d[i][j][q] = 0.0f;

    load_stage(0, 0);
    load_stage(1, 1);

    const int lr = l & 15;        // ldmatrix row-within-16
    const int lk = l >> 4;        // ldmatrix k-half (16B group select)

#pragma unroll 1
    for (int kc = 0; kc < K_CHUNKS; ++kc) {
        CP_WAIT1();               // chunk kc fully arrived (kc+1 may be in flight)
        __syncthreads();          // all warps done reading stage being reloaded
        if (kc + 2 < K_CHUNKS) load_stage((kc + 2) % STAGES, kc + 2);

        const int s = kc % STAGES;
        const uint32_t sa = smem_base + s * STAGE_BYTES;
        const uint32_t sb = sa + A_BYTES;

#pragma unroll
        for (int ks = 0; ks < 4; ++ks) {    // 4 x (k=32 fp8) per 128B chunk
            uint32_t a[2][4], bf[4][4];
            const int kg = ks * 2 + lk;     // 16B group index (0..7)
#pragma unroll
            for (int mi = 0; mi < 2; mi++) {
                const int r = warp_m + mi * 16 + lr;
                ldmatrix_x4(a[mi][0], a[mi][1], a[mi][2], a[mi][3],
                            sa + r * 128 + (((kg ^ (r & 7)) & 7) << 4));
            }
#pragma unroll
            for (int j = 0; j < 4; j++) {
                const int r = warp_n + j * 16 + lr;
                ldmatrix_x4(bf[j][0], bf[j][1], bf[j][2], bf[j][3],
                            sb + r * 128 + (((kg ^ (r & 7)) & 7) << 4));
            }
#pragma unroll
            for (int mi = 0; mi < 2; mi++)
#pragma unroll
                for (int nj = 0; nj < 8; nj++) {
                    const int j = nj >> 1, h = nj & 1;
                    mma_e4m3(d[mi][nj], a[mi], bf[j][h], bf[j][2 + h]);
                }
        }
    }
    CP_WAIT0();

    // ---- epilogue: dequant + bias, bf16-round, f32 stores ----
    const float inv = 1.0f / (xs[0] * ws[0]);
    const int mrow = mt * BM + warp_m + (l >> 2);
    const int ncol0 = nt * BN + warp_n + 2 * (l & 3);

#pragma unroll
    for (int nj = 0; nj < 8; nj++) {
        const int n = ncol0 + nj * 8;
        const float b0 = bias[n];
        const float b1 = bias[n + 1];
#pragma unroll
        for (int mi = 0; mi < 2; mi++) {
            const int m0 = mrow + mi * 16;
            float f0 = __bfloat162float(__float2bfloat16_rn(d[mi][nj][0] * inv + b0));
            float f1 = __bfloat162float(__float2bfloat16_rn(d[mi][nj][1] * inv + b1));
            float f2 = __bfloat162float(__float2bfloat16_rn(d[mi][nj][2] * inv + b0));
            float f3 = __bfloat162float(__float2bfloat16_rn(d[mi][nj][3] * inv + b1));
            *reinterpret_cast<float2*>(out + (size_t)m0 * GN + n) = make_float2(f0, f1);
            *reinterpret_cast<float2*>(out + (size_t)(m0 + 8) * GN + n) = make_float2(f2, f3);
        }
    }
}

// ============================================================================
// kernel_launch — inputs identified by element count
// ============================================================================
extern "C" void kernel_launch(void* const* d_in, const int* in_sizes, int n_in,
                              void* d_out, int out_size) {
    const float* x = nullptr;
    const float* wgt = nullptr;
    const float* bias = nullptr;
    const float* scales[3] = {nullptr, nullptr, nullptr};
    int ns = 0;
    for (int i = 0; i < n_in; i++) {
        const int sz = in_sizes[i];
        if (sz == GM * GK)      x    = (const float*)d_in[i];
        else if (sz == GN * GK) wgt  = (const float*)d_in[i];
        else if (sz == GN)      bias = (const float*)d_in[i];
        else if (sz == 1 && ns < 3) scales[ns++] = (const float*)d_in[i];
    }
    const float* xs = scales[0];   // x_scale (first size-1 input)
    const float* ws = scales[1];   // w_scale (second size-1 input)
    float* out = (float*)d_out;

    {
        const int total = X_TOTAL8 + W_TOTAL8;          // 6,291,456 threads
        quant_both_kernel<<<total / 256, 256>>>(x, wgt, xs, ws);
    }

    cudaFuncSetAttribute(gemm_kernel, cudaFuncAttributeMaxDynamicSharedMemorySize, SMEM_TOTAL);
    dim3 grid(GN / BN, GM / BM);   // (32, 64) = 2048 CTAs, 2/SM
    gemm_kernel<<<grid, THREADS, SMEM_TOTAL>>>(bias, xs, ws, out);
}